// round 15
// baseline (speedup 1.0000x reference)
#include <cuda_runtime.h>
#include <cstdint>
#include <math.h>

#define N_NODES 50000
#define N_EDGES 500000
#define D 128
#define NBLK 148
#define NTHR 1024
#define NTOT (NBLK * NTHR)          // 151552 threads
#define NW   (NTOT / 32)            // 4736 warps
#define EPT 4                        // max edges per thread

// ---------------- device state (zero-init at load; self-rezeroed each run) --
__device__ int   g_barc[3];          // arrive counters (self-resetting)
__device__ int   g_gen[3];           // release generations (monotonic)
__device__ float g_deg[N_NODES];     // weighted in-degree (re-zeroed in P3)
__device__ float g_y0[N_NODES];      // X @ w (overwritten each run)
__device__ float g_q1[N_NODES];      // sum dinv[s]*ew*y0[s]        (re-zeroed)
__device__ float g_q2[N_NODES];      // sum dinv[s]*ew*(t1[s]+c1)   (re-zeroed)

// sense-reversing grid barrier: no host-side reset needed across replays
__device__ __forceinline__ void gbar(int i) {
    __syncthreads();
    if (threadIdx.x == 0) {
        int gen = __ldcg(&g_gen[i]);
        __threadfence();
        int ticket = atomicAdd(&g_barc[i], 1);
        if (ticket == NBLK - 1) {
            atomicExch(&g_barc[i], 0);       // reset for next replay
            __threadfence();
            atomicAdd(&g_gen[i], 1);         // release
        } else {
            while (__ldcg(&g_gen[i]) == gen) __nanosleep(20);
        }
        __threadfence();
    }
    __syncthreads();
}

// warp dot: row_t(M) . v, v held as per-lane float4
__device__ __forceinline__ float warp_dot_row(const float* __restrict__ M,
                                              int t, const float4 vv, int lane) {
    float4 m = *(const float4*)(M + (size_t)t * D + lane * 4);
    float d = m.x * vv.x + m.y * vv.y + m.z * vv.z + m.w * vv.w;
    #pragma unroll
    for (int o = 16; o > 0; o >>= 1)
        d += __shfl_xor_sync(0xFFFFFFFFu, d, o);
    return d;
}

__global__ __launch_bounds__(NTHR, 1) void fused_kernel(
    const float* __restrict__ x,  const void* __restrict__ ei,
    const float* __restrict__ ew,
    const float* __restrict__ W1, const float* __restrict__ b1,
    const float* __restrict__ W2, const float* __restrict__ b2,
    const float* __restrict__ Wf, const float* __restrict__ bf,
    float* __restrict__ out)
{
    __shared__ unsigned int s_acc;
    __shared__ __align__(16) float s_v2[D];
    __shared__ __align__(16) float s_w[D];
    __shared__ float s_c1, s_c2;

    const int tid  = threadIdx.x;
    const int bid  = blockIdx.x;
    const int gt   = bid * NTHR + tid;
    const int wid  = tid >> 5, lane = tid & 31;

    // ====== P0: decode+deg first (launch 10MB edge stream), then weight
    //        collapse (overlaps edge traffic), then 4-deep GEMV.
    if (tid == 0) s_acc = 0u;
    __syncthreads();
    unsigned int probe = ((const unsigned int*)ei)[2 * tid + 1];
    if (probe) atomicOr(&s_acc, probe);
    __syncthreads();
    const int is64 = (s_acc == 0u) ? 1 : 0;

    // decode edges into registers + deg atomics (deg pre-zeroed by last run)
    int es[EPT], ed[EPT];
    float eev[EPT];
    #pragma unroll
    for (int i = 0; i < EPT; i++) {
        int e = gt + i * NTOT;
        es[i] = 0; ed[i] = 0; eev[i] = 0.0f;
        if (e < N_EDGES) {
            int s, d;
            if (is64) {
                const long long* p = (const long long*)ei;
                s = (int)p[e]; d = (int)p[N_EDGES + e];
            } else {
                const int* p = (const int*)ei;
                s = p[e]; d = p[N_EDGES + e];
            }
            es[i] = s; ed[i] = d;
            float w = ew[e];
            eev[i] = w;
            atomicAdd(&g_deg[d], w);
        }
    }

    // weight collapse: v2 = W2@Wf, then w = W1@v2, c1, c2 (per-block, smem)
    {
        float4 wf4 = *(const float4*)(Wf + lane * 4);
        #pragma unroll
        for (int r = 0; r < 4; r++) {
            int t = wid * 4 + r;
            float d = warp_dot_row(W2, t, wf4, lane);
            if (lane == 0) s_v2[t] = d;
        }
        __syncthreads();
        float4 v24 = *(const float4*)(s_v2 + lane * 4);
        #pragma unroll
        for (int r = 0; r < 4; r++) {
            int t = wid * 4 + r;
            float d = warp_dot_row(W1, t, v24, lane);
            if (lane == 0) s_w[t] = d;
        }
        if (wid == 0) {
            float4 a = *(const float4*)(b1 + lane * 4);
            float d = a.x * v24.x + a.y * v24.y + a.z * v24.z + a.w * v24.w;
            #pragma unroll
            for (int o = 16; o > 0; o >>= 1)
                d += __shfl_xor_sync(0xFFFFFFFFu, d, o);
            if (lane == 0) s_c1 = d;
        }
        if (wid == 1) {
            float4 a = *(const float4*)(b2 + lane * 4);
            float4 b = *(const float4*)(Wf + lane * 4);
            float d = a.x * b.x + a.y * b.y + a.z * b.z + a.w * b.w;
            #pragma unroll
            for (int o = 16; o > 0; o >>= 1)
                d += __shfl_xor_sync(0xFFFFFFFFu, d, o);
            if (lane == 0) s_c2 = d + bf[0];
        }
    }
    __syncthreads();

    // GEMV y0 = X @ w: 4 rows in flight per warp (coalesced streaming)
    {
        int gwarp = gt >> 5;
        float4 wv4 = *(const float4*)(s_w + lane * 4);
        for (int n = gwarp; n < N_NODES; n += 4 * NW) {
            int n1 = n + NW, n2 = n + 2 * NW, n3 = n + 3 * NW;
            float d0 = 0.f, d1 = 0.f, d2 = 0.f, d3 = 0.f;
            {
                float4 a = *(const float4*)(x + (size_t)n * D + lane * 4);
                d0 = a.x * wv4.x + a.y * wv4.y + a.z * wv4.z + a.w * wv4.w;
            }
            if (n1 < N_NODES) {
                float4 a = *(const float4*)(x + (size_t)n1 * D + lane * 4);
                d1 = a.x * wv4.x + a.y * wv4.y + a.z * wv4.z + a.w * wv4.w;
            }
            if (n2 < N_NODES) {
                float4 a = *(const float4*)(x + (size_t)n2 * D + lane * 4);
                d2 = a.x * wv4.x + a.y * wv4.y + a.z * wv4.z + a.w * wv4.w;
            }
            if (n3 < N_NODES) {
                float4 a = *(const float4*)(x + (size_t)n3 * D + lane * 4);
                d3 = a.x * wv4.x + a.y * wv4.y + a.z * wv4.z + a.w * wv4.w;
            }
            #pragma unroll
            for (int o = 16; o > 0; o >>= 1) {
                d0 += __shfl_xor_sync(0xFFFFFFFFu, d0, o);
                d1 += __shfl_xor_sync(0xFFFFFFFFu, d1, o);
                d2 += __shfl_xor_sync(0xFFFFFFFFu, d2, o);
                d3 += __shfl_xor_sync(0xFFFFFFFFu, d3, o);
            }
            if (lane == 0) {
                g_y0[n] = d0;
                if (n1 < N_NODES) g_y0[n1] = d1;
                if (n2 < N_NODES) g_y0[n2] = d2;
                if (n3 < N_NODES) g_y0[n3] = d3;
            }
        }
    }
    gbar(0);

    // ====== P1: edge pass 1 — q1[d] += dinv[s]*ew*y0[s]
    float ea[EPT], edis[EPT], ey0[EPT];
    #pragma unroll
    for (int i = 0; i < EPT; i++) {
        int e = gt + i * NTOT;
        ea[i] = 0.0f; edis[i] = 0.0f; ey0[i] = 0.0f;
        if (e < N_EDGES) {
            int s = es[i];
            float dis = rsqrtf(__ldcg(&g_deg[s]) + 1.0f);
            float a   = dis * eev[i];
            float y0s = __ldcg(&g_y0[s]);
            edis[i] = dis; ea[i] = a; ey0[i] = y0s;
            atomicAdd(&g_q1[ed[i]], a * y0s);
        }
    }
    gbar(1);

    // ====== P2: edge pass 2 — q2[d] += dinv[s]*ew*(t1[s] + c1)
    {
        float c1 = s_c1;
        #pragma unroll
        for (int i = 0; i < EPT; i++) {
            int e = gt + i * NTOT;
            if (e < N_EDGES) {
                float dis = edis[i];
                float t1s = dis * (dis * ey0[i] + __ldcg(&g_q1[es[i]])) + c1;
                atomicAdd(&g_q2[ed[i]], ea[i] * t1s);
            }
        }
    }
    gbar(2);

    // ====== P3: final head + re-zero accumulators for next replay
    {
        float c1 = s_c1, c2 = s_c2;
        for (int n = gt; n < N_NODES; n += NTOT) {
            float di  = rsqrtf(__ldcg(&g_deg[n]) + 1.0f);
            float sl  = di * di;
            float t1  = di * (di * __ldcg(&g_y0[n]) + __ldcg(&g_q1[n]));
            float z   = sl * (t1 + c1) + di * __ldcg(&g_q2[n]) + c2;
            out[n] = 10.0f / (1.0f + expf(-z));
            g_deg[n] = 0.0f; g_q1[n] = 0.0f; g_q2[n] = 0.0f;
        }
    }
}

// ================= launcher =================
extern "C" void kernel_launch(void* const* d_in, const int* in_sizes, int n_in,
                              void* d_out, int out_size) {
    const float* x  = (const float*)d_in[0];
    const void*  ei = d_in[1];
    const float* ew = (const float*)d_in[2];
    const float* W1 = (const float*)d_in[3];
    const float* b1 = (const float*)d_in[4];
    const float* W2 = (const float*)d_in[5];
    const float* b2 = (const float*)d_in[6];
    const float* Wf = (const float*)d_in[7];
    const float* bf = (const float*)d_in[8];
    float* out = (float*)d_out;

    fused_kernel<<<NBLK, NTHR>>>(x, ei, ew, W1, b1, W2, b2, Wf, bf, out);
}

// round 16
// speedup vs baseline: 1.0077x; 1.0077x over previous
#include <cuda_runtime.h>
#include <cstdint>
#include <math.h>

#define N_NODES 50000
#define N_EDGES 500000
#define D 128
#define NBLK 148
#define NTHR 1024
#define NTOT (NBLK * NTHR)          // 151552 threads
#define NW   (NTOT / 32)            // 4736 warps
#define EPT 4                        // max edges per thread
#define NSLOT 8

// ---------------- device state (zero-init at load; self-rezeroed each run) --
__device__ int   g_slot[3][NSLOT];   // spread arrive counters (self-resetting)
__device__ int   g_master[3];        // slot-level counter (self-resetting)
__device__ int   g_gen[3];           // release generations (monotonic)
__device__ float g_deg[N_NODES];     // weighted in-degree (re-zeroed in P3)
__device__ float g_y0[N_NODES];      // X @ w (overwritten each run)
__device__ float g_q1[N_NODES];      // sum dinv[s]*ew*y0[s]        (re-zeroed)
__device__ float g_q2[N_NODES];      // sum dinv[s]*ew*(t1[s]+c1)   (re-zeroed)

// blocks with bid % NSLOT == s : count = ceil((NBLK - s) / NSLOT)
__device__ __forceinline__ int slot_count(int s) {
    return (NBLK - s + NSLOT - 1) / NSLOT;
}

// two-level sense-reversing grid barrier (low same-address contention)
__device__ __forceinline__ void gbar(int i) {
    __syncthreads();
    if (threadIdx.x == 0) {
        int gen = __ldcg(&g_gen[i]);
        __threadfence();
        int slot = blockIdx.x & (NSLOT - 1);
        int t = atomicAdd(&g_slot[i][slot], 1);
        if (t == slot_count(slot) - 1) {
            atomicExch(&g_slot[i][slot], 0);          // reset slot
            int m = atomicAdd(&g_master[i], 1);
            if (m == NSLOT - 1) {
                atomicExch(&g_master[i], 0);          // reset master
                __threadfence();
                atomicAdd(&g_gen[i], 1);              // release
            }
        }
        while (__ldcg(&g_gen[i]) == gen) __nanosleep(16);
        __threadfence();
    }
    __syncthreads();
}

// warp dot: row_t(M) . v, v held as per-lane float4
__device__ __forceinline__ float warp_dot_row(const float* __restrict__ M,
                                              int t, const float4 vv, int lane) {
    float4 m = *(const float4*)(M + (size_t)t * D + lane * 4);
    float d = m.x * vv.x + m.y * vv.y + m.z * vv.z + m.w * vv.w;
    #pragma unroll
    for (int o = 16; o > 0; o >>= 1)
        d += __shfl_xor_sync(0xFFFFFFFFu, d, o);
    return d;
}

__global__ __launch_bounds__(NTHR, 1) void fused_kernel(
    const float* __restrict__ x,  const void* __restrict__ ei,
    const float* __restrict__ ew,
    const float* __restrict__ W1, const float* __restrict__ b1,
    const float* __restrict__ W2, const float* __restrict__ b2,
    const float* __restrict__ Wf, const float* __restrict__ bf,
    float* __restrict__ out)
{
    __shared__ unsigned int s_acc;
    __shared__ __align__(16) float s_v2[D];
    __shared__ __align__(16) float s_w[D];
    __shared__ float s_c1, s_c2;

    const int tid  = threadIdx.x;
    const int bid  = blockIdx.x;
    const int gt   = bid * NTHR + tid;
    const int wid  = tid >> 5, lane = tid & 31;

    // ====== P0: decode+deg (10MB edge stream first), weight collapse, GEMV
    if (tid == 0) s_acc = 0u;
    __syncthreads();
    unsigned int probe = ((const unsigned int*)ei)[2 * tid + 1];
    if (probe) atomicOr(&s_acc, probe);
    __syncthreads();
    const int is64 = (s_acc == 0u) ? 1 : 0;

    int es[EPT], ed[EPT];
    float eev[EPT];
    #pragma unroll
    for (int i = 0; i < EPT; i++) {
        int e = gt + i * NTOT;
        es[i] = 0; ed[i] = 0; eev[i] = 0.0f;
        if (e < N_EDGES) {
            int s, d;
            if (is64) {
                const long long* p = (const long long*)ei;
                s = (int)p[e]; d = (int)p[N_EDGES + e];
            } else {
                const int* p = (const int*)ei;
                s = p[e]; d = p[N_EDGES + e];
            }
            es[i] = s; ed[i] = d;
            float w = ew[e];
            eev[i] = w;
            atomicAdd(&g_deg[d], w);
        }
    }

    // weight collapse: v2 = W2@Wf, then w = W1@v2, c1, c2 (per-block, smem)
    {
        float4 wf4 = *(const float4*)(Wf + lane * 4);
        #pragma unroll
        for (int r = 0; r < 4; r++) {
            int t = wid * 4 + r;
            float d = warp_dot_row(W2, t, wf4, lane);
            if (lane == 0) s_v2[t] = d;
        }
        __syncthreads();
        float4 v24 = *(const float4*)(s_v2 + lane * 4);
        #pragma unroll
        for (int r = 0; r < 4; r++) {
            int t = wid * 4 + r;
            float d = warp_dot_row(W1, t, v24, lane);
            if (lane == 0) s_w[t] = d;
        }
        if (wid == 0) {
            float4 a = *(const float4*)(b1 + lane * 4);
            float d = a.x * v24.x + a.y * v24.y + a.z * v24.z + a.w * v24.w;
            #pragma unroll
            for (int o = 16; o > 0; o >>= 1)
                d += __shfl_xor_sync(0xFFFFFFFFu, d, o);
            if (lane == 0) s_c1 = d;
        }
        if (wid == 1) {
            float4 a = *(const float4*)(b2 + lane * 4);
            float4 b = *(const float4*)(Wf + lane * 4);
            float d = a.x * b.x + a.y * b.y + a.z * b.z + a.w * b.w;
            #pragma unroll
            for (int o = 16; o > 0; o >>= 1)
                d += __shfl_xor_sync(0xFFFFFFFFu, d, o);
            if (lane == 0) s_c2 = d + bf[0];
        }
    }
    __syncthreads();

    // GEMV y0 = X @ w: 4 rows in flight per warp (coalesced streaming)
    {
        int gwarp = gt >> 5;
        float4 wv4 = *(const float4*)(s_w + lane * 4);
        for (int n = gwarp; n < N_NODES; n += 4 * NW) {
            int n1 = n + NW, n2 = n + 2 * NW, n3 = n + 3 * NW;
            float d0 = 0.f, d1 = 0.f, d2 = 0.f, d3 = 0.f;
            {
                float4 a = *(const float4*)(x + (size_t)n * D + lane * 4);
                d0 = a.x * wv4.x + a.y * wv4.y + a.z * wv4.z + a.w * wv4.w;
            }
            if (n1 < N_NODES) {
                float4 a = *(const float4*)(x + (size_t)n1 * D + lane * 4);
                d1 = a.x * wv4.x + a.y * wv4.y + a.z * wv4.z + a.w * wv4.w;
            }
            if (n2 < N_NODES) {
                float4 a = *(const float4*)(x + (size_t)n2 * D + lane * 4);
                d2 = a.x * wv4.x + a.y * wv4.y + a.z * wv4.z + a.w * wv4.w;
            }
            if (n3 < N_NODES) {
                float4 a = *(const float4*)(x + (size_t)n3 * D + lane * 4);
                d3 = a.x * wv4.x + a.y * wv4.y + a.z * wv4.z + a.w * wv4.w;
            }
            #pragma unroll
            for (int o = 16; o > 0; o >>= 1) {
                d0 += __shfl_xor_sync(0xFFFFFFFFu, d0, o);
                d1 += __shfl_xor_sync(0xFFFFFFFFu, d1, o);
                d2 += __shfl_xor_sync(0xFFFFFFFFu, d2, o);
                d3 += __shfl_xor_sync(0xFFFFFFFFu, d3, o);
            }
            if (lane == 0) {
                g_y0[n] = d0;
                if (n1 < N_NODES) g_y0[n1] = d1;
                if (n2 < N_NODES) g_y0[n2] = d2;
                if (n3 < N_NODES) g_y0[n3] = d3;
            }
        }
    }
    gbar(0);

    // ====== P1: edge pass 1 — q1[d] += dinv[s]*ew*y0[s]
    float ea[EPT], edis[EPT], ey0[EPT];
    #pragma unroll
    for (int i = 0; i < EPT; i++) {
        int e = gt + i * NTOT;
        ea[i] = 0.0f; edis[i] = 0.0f; ey0[i] = 0.0f;
        if (e < N_EDGES) {
            int s = es[i];
            float dis = rsqrtf(__ldcg(&g_deg[s]) + 1.0f);
            float a   = dis * eev[i];
            float y0s = __ldcg(&g_y0[s]);
            edis[i] = dis; ea[i] = a; ey0[i] = y0s;
            atomicAdd(&g_q1[ed[i]], a * y0s);
        }
    }
    gbar(1);

    // ====== P2: edge pass 2 — q2[d] += dinv[s]*ew*(t1[s] + c1)
    {
        float c1 = s_c1;
        #pragma unroll
        for (int i = 0; i < EPT; i++) {
            int e = gt + i * NTOT;
            if (e < N_EDGES) {
                float dis = edis[i];
                float t1s = dis * (dis * ey0[i] + __ldcg(&g_q1[es[i]])) + c1;
                atomicAdd(&g_q2[ed[i]], ea[i] * t1s);
            }
        }
    }
    gbar(2);

    // ====== P3: final head first, then re-zero accumulators for next replay
    {
        float c1 = s_c1, c2 = s_c2;
        for (int n = gt; n < N_NODES; n += NTOT) {
            float di  = rsqrtf(__ldcg(&g_deg[n]) + 1.0f);
            float sl  = di * di;
            float t1  = di * (di * __ldcg(&g_y0[n]) + __ldcg(&g_q1[n]));
            float z   = sl * (t1 + c1) + di * __ldcg(&g_q2[n]) + c2;
            out[n] = 10.0f / (1.0f + expf(-z));
        }
        for (int n = gt; n < N_NODES; n += NTOT) {
            g_deg[n] = 0.0f; g_q1[n] = 0.0f; g_q2[n] = 0.0f;
        }
    }
}

// ================= launcher =================
extern "C" void kernel_launch(void* const* d_in, const int* in_sizes, int n_in,
                              void* d_out, int out_size) {
    const float* x  = (const float*)d_in[0];
    const void*  ei = d_in[1];
    const float* ew = (const float*)d_in[2];
    const float* W1 = (const float*)d_in[3];
    const float* b1 = (const float*)d_in[4];
    const float* W2 = (const float*)d_in[5];
    const float* b2 = (const float*)d_in[6];
    const float* Wf = (const float*)d_in[7];
    const float* bf = (const float*)d_in[8];
    float* out = (float*)d_out;

    fused_kernel<<<NBLK, NTHR>>>(x, ei, ew, W1, b1, W2, b2, Wf, bf, out);
}